// round 5
// baseline (speedup 1.0000x reference)
#include <cuda_runtime.h>
#include <stdint.h>

#define NN  50000
#define NE  800000
#define FIN 512
#define FH  256
#define FO  128

// ---- scratch: __device__ globals ----
__device__ int   g_is64;
__device__ __align__(16) float g_dinv[NN];
__device__ __align__(16) int   g_cnt [NN];
__device__ __align__(16) int   g_off [NN + 1];
__device__ __align__(16) int   g_fill[NN];
__device__ __align__(16) int   g_csr_src[NE];
__device__ __align__(16) float g_csr_w  [NE];
__device__ __align__(16) float g_h1  [(size_t)NN * FH];
__device__ __align__(16) float g_agg1[(size_t)NN * FH];
__device__ __align__(16) float g_h2  [(size_t)NN * FO];

// ---------------------------------------------------------------------------
// edge dtype detect + decode
// ---------------------------------------------------------------------------
__global__ void k_detect(const void* __restrict__ ei) {
    if (threadIdx.x == 0 && blockIdx.x == 0) {
        const long long* p = (const long long*)ei;
        int ok = 1;
        for (int i = 0; i < 4096; i++) {
            long long v = p[i];
            if (v < 0 || v >= NN) { ok = 0; break; }
        }
        g_is64 = ok;
    }
}

__device__ __forceinline__ unsigned eidx(const void* __restrict__ ei, size_t idx) {
    if (g_is64) return (unsigned)((const long long*)ei)[idx];
    return (unsigned)((const int*)ei)[idx];
}

// ---------------------------------------------------------------------------
// degree / normalization / CSR build
// ---------------------------------------------------------------------------
__global__ void k_init() {
    int i = blockIdx.x * blockDim.x + threadIdx.x;
    if (i < NN) { g_cnt[i] = 0; g_fill[i] = 0; }
}

__global__ void k_deg_count(const void* __restrict__ ei) {
    int i = blockIdx.x * blockDim.x + threadIdx.x;
    if (i < NE) {
        unsigned d = eidx(ei, (size_t)NE + i);
        if (d < NN) atomicAdd(&g_cnt[d], 1);
    }
}

__global__ void k_dinv() {
    int i = blockIdx.x * blockDim.x + threadIdx.x;
    if (i < NN) g_dinv[i] = rsqrtf((float)(g_cnt[i] + 1));   // +1 self-loop
}

// single-block exclusive scan of g_cnt -> g_off
__global__ void k_scan() {
    __shared__ int sh[1024];
    __shared__ int carry;
    const int tid = threadIdx.x;
    if (tid == 0) carry = 0;
    __syncthreads();

    for (int base = 0; base < NN; base += 1024) {
        int i = base + tid;
        int v = (i < NN) ? g_cnt[i] : 0;
        sh[tid] = v;
        __syncthreads();
        for (int ofs = 1; ofs < 1024; ofs <<= 1) {
            int t = (tid >= ofs) ? sh[tid - ofs] : 0;
            __syncthreads();
            sh[tid] += t;
            __syncthreads();
        }
        if (i < NN) g_off[i] = carry + sh[tid] - v;
        __syncthreads();
        if (tid == 1023) carry += sh[1023];
        __syncthreads();
    }
    if (tid == 0) g_off[NN] = carry;
}

__global__ void k_fill(const void* __restrict__ ei) {
    int i = blockIdx.x * blockDim.x + threadIdx.x;
    if (i < NE) {
        unsigned s = eidx(ei, i);
        unsigned d = eidx(ei, (size_t)NE + i);
        if (s < NN && d < NN) {
            int pos = g_off[d] + atomicAdd(&g_fill[d], 1);
            if (pos < NE) {
                g_csr_src[pos] = (int)s;
                g_csr_w[pos]   = g_dinv[s] * g_dinv[d];
            }
        }
    }
}

// ---------------------------------------------------------------------------
// fp32 SGEMM: C = A[M,K] @ B[K,N], BM=BN=64, BK=16, 256 thr, 4x4 microtile
// layer 0: A = x (param), C = g_h1 ;  layer 1: A = g_agg1, C = g_h2
// ---------------------------------------------------------------------------
__global__ void sgemm64(const float* __restrict__ Aext,
                        const float* __restrict__ B,
                        int layer, int M, int N, int K) {
    const float* A = (layer == 0) ? Aext : (const float*)g_agg1;
    float*       C = (layer == 0) ? g_h1 : g_h2;

    __shared__ float As[16][64];
    __shared__ float Bs[16][64];

    const int tid = threadIdx.x;
    const int tx  = tid & 15;
    const int ty  = tid >> 4;
    const int row0 = blockIdx.y * 64;
    const int col0 = blockIdx.x * 64;

    float acc[4][4] = {};

    for (int k0 = 0; k0 < K; k0 += 16) {
        #pragma unroll
        for (int i = 0; i < 4; i++) {
            int idx = tid + i * 256;
            int r = idx >> 4, c = idx & 15;
            int gr = row0 + r;
            As[c][r] = (gr < M) ? A[(size_t)gr * K + k0 + c] : 0.0f;
            int rb = idx >> 6, cb = idx & 63;
            Bs[rb][cb] = B[(size_t)(k0 + rb) * N + col0 + cb];
        }
        __syncthreads();

        #pragma unroll
        for (int kk = 0; kk < 16; kk++) {
            float4 a4 = *(const float4*)&As[kk][ty * 4];
            float4 b4 = *(const float4*)&Bs[kk][tx * 4];
            float a[4] = {a4.x, a4.y, a4.z, a4.w};
            float b[4] = {b4.x, b4.y, b4.z, b4.w};
            #pragma unroll
            for (int i = 0; i < 4; i++)
                #pragma unroll
                for (int j = 0; j < 4; j++)
                    acc[i][j] += a[i] * b[j];
        }
        __syncthreads();
    }

    #pragma unroll
    for (int i = 0; i < 4; i++) {
        int r = row0 + ty * 4 + i;
        if (r < M) {
            #pragma unroll
            for (int j = 0; j < 4; j++)
                C[(size_t)r * N + col0 + tx * 4 + j] = acc[i][j];
        }
    }
}

// ---------------------------------------------------------------------------
// CSR gather: out[i,:] = dinv[i]^2*h[i,:] + sum_e w_e*h[src_e,:] + bias
// ---------------------------------------------------------------------------
template<int LAYER>
__global__ void k_gather(const float* __restrict__ bias,
                         float* __restrict__ outext) {
    constexpr int F = (LAYER == 0) ? FH : FO;
    constexpr int V = F / 128;
    const float* h   = (LAYER == 0) ? (const float*)g_h1 : (const float*)g_h2;
    float*       out = (LAYER == 0) ? g_agg1 : outext;

    int node = (blockIdx.x * blockDim.x + threadIdx.x) >> 5;
    int lane = threadIdx.x & 31;
    if (node >= NN) return;

    float4 acc[V];
    float wi = g_dinv[node];
    wi *= wi;
    const float4* hr = (const float4*)(h + (size_t)node * F);
    #pragma unroll
    for (int v = 0; v < V; v++) {
        float4 t = hr[lane + 32 * v];
        acc[v] = make_float4(wi * t.x, wi * t.y, wi * t.z, wi * t.w);
    }

    int beg = g_off[node];
    int end = beg + g_cnt[node];
    for (int e = beg; e < end; e++) {
        int   s = g_csr_src[e];
        float w = g_csr_w[e];
        const float4* sr = (const float4*)(h + (size_t)s * F);
        #pragma unroll
        for (int v = 0; v < V; v++) {
            float4 t = sr[lane + 32 * v];
            acc[v].x += w * t.x; acc[v].y += w * t.y;
            acc[v].z += w * t.z; acc[v].w += w * t.w;
        }
    }

    const float4* bv = (const float4*)bias;
    float4* ov = (float4*)(out + (size_t)node * F);
    #pragma unroll
    for (int v = 0; v < V; v++) {
        float4 b = bv[lane + 32 * v];
        float4 o = make_float4(acc[v].x + b.x, acc[v].y + b.y,
                               acc[v].z + b.z, acc[v].w + b.w);
        if (LAYER == 0) {
            o.x = fmaxf(o.x, 0.f); o.y = fmaxf(o.y, 0.f);
            o.z = fmaxf(o.z, 0.f); o.w = fmaxf(o.w, 0.f);
        }
        ov[lane + 32 * v] = o;
    }
}

// ---------------------------------------------------------------------------
// launch — inputs identified by element count (order-proof)
// ---------------------------------------------------------------------------
extern "C" void kernel_launch(void* const* d_in, const int* in_sizes, int n_in,
                              void* d_out, int out_size) {
    const float* x  = nullptr;
    const void*  ei = nullptr;
    const float* W1 = nullptr;
    const float* b1 = nullptr;
    const float* W2 = nullptr;
    const float* b2 = nullptr;

    for (int i = 0; i < n_in; i++) {
        switch (in_sizes[i]) {
            case NN * FIN:   x  = (const float*)d_in[i]; break;  // 25,600,000
            case 2 * NE:     ei = d_in[i];               break;  //  1,600,000
            case FIN * FH:   W1 = (const float*)d_in[i]; break;  //    131,072
            case FH:         b1 = (const float*)d_in[i]; break;  //        256
            case FH * FO:    W2 = (const float*)d_in[i]; break;  //     32,768
            case FO:         b2 = (const float*)d_in[i]; break;  //        128
            default: break;
        }
    }
    float* out = (float*)d_out;

    const int T = 256;

    k_detect   <<<1, 32>>>(ei);
    k_init     <<<(NN + T - 1) / T, T>>>();
    k_deg_count<<<(NE + T - 1) / T, T>>>(ei);
    k_dinv     <<<(NN + T - 1) / T, T>>>();
    k_scan     <<<1, 1024>>>();
    k_fill     <<<(NE + T - 1) / T, T>>>(ei);

    // layer 1: h1 = x @ W1 ; agg1 = relu(A_hat h1 + b1)
    {
        dim3 grid(FH / 64, (NN + 63) / 64);
        sgemm64<<<grid, 256>>>(x, W1, 0, NN, FH, FIN);
    }
    k_gather<0><<<((size_t)NN * 32 + T - 1) / T, T>>>(b1, nullptr);

    // layer 2: h2 = agg1 @ W2 ; out = A_hat h2 + b2
    {
        dim3 grid(FO / 64, (NN + 63) / 64);
        sgemm64<<<grid, 256>>>(nullptr, W2, 1, NN, FO, FH);
    }
    k_gather<1><<<((size_t)NN * 32 + T - 1) / T, T>>>(b2, out);
}

// round 6
// speedup vs baseline: 1.3462x; 1.3462x over previous
#include <cuda_runtime.h>
#include <stdint.h>

#define NN  50000
#define NE  800000
#define FIN 512
#define FH  256
#define FO  128

// ---- scratch: __device__ globals ----
__device__ int   g_is64;
__device__ __align__(16) float g_dinv[NN];
__device__ __align__(16) int   g_cnt [NN];
__device__ __align__(16) int   g_off [NN + 1];
__device__ __align__(16) int   g_fill[NN];
__device__ __align__(16) int   g_csr_src[NE];
__device__ __align__(16) float g_csr_w  [NE];
__device__ __align__(16) float g_h1  [(size_t)NN * FH];
__device__ __align__(16) float g_agg1[(size_t)NN * FH];
__device__ __align__(16) float g_h2  [(size_t)NN * FO];

// ---------------------------------------------------------------------------
// edge dtype detect (parallel, 2048 samples) + decode
// ---------------------------------------------------------------------------
__global__ void k_detect(const void* __restrict__ ei) {
    const long long* p = (const long long*)ei;
    int lane = threadIdx.x;
    int bad = 0;
    #pragma unroll 4
    for (int i = lane; i < 2048; i += 32) {
        long long v = p[i];
        if (v < 0 || v >= NN) bad = 1;
    }
    unsigned m = __ballot_sync(0xffffffffu, bad);
    if (lane == 0) g_is64 = (m == 0);
}

__device__ __forceinline__ unsigned eidx(const void* __restrict__ ei, size_t idx) {
    if (g_is64) return (unsigned)((const long long*)ei)[idx];
    return (unsigned)((const int*)ei)[idx];
}

// ---------------------------------------------------------------------------
// degree / normalization / CSR build
// ---------------------------------------------------------------------------
__global__ void k_init() {
    int i = blockIdx.x * blockDim.x + threadIdx.x;
    if (i < NN) { g_cnt[i] = 0; g_fill[i] = 0; }
}

__global__ void k_deg_count(const void* __restrict__ ei) {
    int i = blockIdx.x * blockDim.x + threadIdx.x;
    if (i < NE) {
        unsigned d = eidx(ei, (size_t)NE + i);
        if (d < NN) atomicAdd(&g_cnt[d], 1);
    }
}

__global__ void k_dinv() {
    int i = blockIdx.x * blockDim.x + threadIdx.x;
    if (i < NN) g_dinv[i] = rsqrtf((float)(g_cnt[i] + 1));   // +1 self-loop
}

// single-block exclusive scan of g_cnt -> g_off
__global__ void k_scan() {
    __shared__ int sh[1024];
    __shared__ int carry;
    const int tid = threadIdx.x;
    if (tid == 0) carry = 0;
    __syncthreads();

    for (int base = 0; base < NN; base += 1024) {
        int i = base + tid;
        int v = (i < NN) ? g_cnt[i] : 0;
        sh[tid] = v;
        __syncthreads();
        for (int ofs = 1; ofs < 1024; ofs <<= 1) {
            int t = (tid >= ofs) ? sh[tid - ofs] : 0;
            __syncthreads();
            sh[tid] += t;
            __syncthreads();
        }
        if (i < NN) g_off[i] = carry + sh[tid] - v;
        __syncthreads();
        if (tid == 1023) carry += sh[1023];
        __syncthreads();
    }
    if (tid == 0) g_off[NN] = carry;
}

__global__ void k_fill(const void* __restrict__ ei) {
    int i = blockIdx.x * blockDim.x + threadIdx.x;
    if (i < NE) {
        unsigned s = eidx(ei, i);
        unsigned d = eidx(ei, (size_t)NE + i);
        if (s < NN && d < NN) {
            int pos = g_off[d] + atomicAdd(&g_fill[d], 1);
            if (pos < NE) {
                g_csr_src[pos] = (int)s;
                g_csr_w[pos]   = g_dinv[s] * g_dinv[d];
            }
        }
    }
}

// ---------------------------------------------------------------------------
// fp32 SGEMM: C = A[M,K] @ B[K,N]; BM=BN=128, BK=16, 256 thr, 8x8 microtile
// layer 0: A = x (param), C = g_h1 ;  layer 1: A = g_agg1, C = g_h2
// ---------------------------------------------------------------------------
#define SPAD 132   // 128 + 4 padding (16B-aligned rows: 132*4=528=33*16)

__global__ void __launch_bounds__(256, 2)
sgemm128(const float* __restrict__ Aext, const float* __restrict__ B,
         int layer, int M, int N, int K) {
    const float* A = (layer == 0) ? Aext : (const float*)g_agg1;
    float*       C = (layer == 0) ? g_h1 : g_h2;

    __shared__ float As[16][SPAD];   // [k][m]
    __shared__ float Bs[16][SPAD];   // [k][n]

    const int tid = threadIdx.x;
    const int tx  = tid & 15;        // 0..15 -> n
    const int ty  = tid >> 4;        // 0..15 -> m
    const int row0 = blockIdx.y * 128;
    const int col0 = blockIdx.x * 128;

    float acc[8][8] = {};

    for (int k0 = 0; k0 < K; k0 += 16) {
        // load A tile 128x16 (2 float4 per thread), store transposed
        #pragma unroll
        for (int i = 0; i < 2; i++) {
            int idx = tid + i * 256;         // 0..511
            int r  = idx >> 2;               // 0..127
            int kq = idx & 3;                // 0..3 (float4 within k)
            int gr = row0 + r;
            float4 av = (gr < M) ? *(const float4*)&A[(size_t)gr * K + k0 + kq * 4]
                                 : make_float4(0.f, 0.f, 0.f, 0.f);
            As[kq * 4 + 0][r] = av.x;
            As[kq * 4 + 1][r] = av.y;
            As[kq * 4 + 2][r] = av.z;
            As[kq * 4 + 3][r] = av.w;
        }
        // load B tile 16x128 (2 float4 per thread), contiguous
        #pragma unroll
        for (int i = 0; i < 2; i++) {
            int idx = tid + i * 256;         // 0..511
            int rb = idx >> 5;               // 0..15
            int cb = idx & 31;               // 0..31
            float4 bv = *(const float4*)&B[(size_t)(k0 + rb) * N + col0 + cb * 4];
            *(float4*)&Bs[rb][cb * 4] = bv;
        }
        __syncthreads();

        #pragma unroll
        for (int kk = 0; kk < 16; kk++) {
            float4 a0 = *(const float4*)&As[kk][ty * 8];
            float4 a1 = *(const float4*)&As[kk][ty * 8 + 4];
            float4 b0 = *(const float4*)&Bs[kk][tx * 8];
            float4 b1 = *(const float4*)&Bs[kk][tx * 8 + 4];
            float a[8] = {a0.x, a0.y, a0.z, a0.w, a1.x, a1.y, a1.z, a1.w};
            float b[8] = {b0.x, b0.y, b0.z, b0.w, b1.x, b1.y, b1.z, b1.w};
            #pragma unroll
            for (int i = 0; i < 8; i++)
                #pragma unroll
                for (int j = 0; j < 8; j++)
                    acc[i][j] += a[i] * b[j];
        }
        __syncthreads();
    }

    // store 8x8 per thread (two float4 per row)
    #pragma unroll
    for (int i = 0; i < 8; i++) {
        int r = row0 + ty * 8 + i;
        if (r < M) {
            float4 o0 = make_float4(acc[i][0], acc[i][1], acc[i][2], acc[i][3]);
            float4 o1 = make_float4(acc[i][4], acc[i][5], acc[i][6], acc[i][7]);
            *(float4*)&C[(size_t)r * N + col0 + tx * 8]     = o0;
            *(float4*)&C[(size_t)r * N + col0 + tx * 8 + 4] = o1;
        }
    }
}

// ---------------------------------------------------------------------------
// CSR gather: out[i,:] = dinv[i]^2*h[i,:] + sum_e w_e*h[src_e,:] + bias
// ---------------------------------------------------------------------------
template<int LAYER>
__global__ void k_gather(const float* __restrict__ bias,
                         float* __restrict__ outext) {
    constexpr int F = (LAYER == 0) ? FH : FO;
    constexpr int V = F / 128;
    const float* h   = (LAYER == 0) ? (const float*)g_h1 : (const float*)g_h2;
    float*       out = (LAYER == 0) ? g_agg1 : outext;

    int node = (blockIdx.x * blockDim.x + threadIdx.x) >> 5;
    int lane = threadIdx.x & 31;
    if (node >= NN) return;

    float4 acc[V];
    float wi = g_dinv[node];
    wi *= wi;
    const float4* hr = (const float4*)(h + (size_t)node * F);
    #pragma unroll
    for (int v = 0; v < V; v++) {
        float4 t = hr[lane + 32 * v];
        acc[v] = make_float4(wi * t.x, wi * t.y, wi * t.z, wi * t.w);
    }

    int beg = g_off[node];
    int end = beg + g_cnt[node];
    for (int e = beg; e < end; e++) {
        int   s = g_csr_src[e];
        float w = g_csr_w[e];
        const float4* sr = (const float4*)(h + (size_t)s * F);
        #pragma unroll
        for (int v = 0; v < V; v++) {
            float4 t = sr[lane + 32 * v];
            acc[v].x += w * t.x; acc[v].y += w * t.y;
            acc[v].z += w * t.z; acc[v].w += w * t.w;
        }
    }

    const float4* bv = (const float4*)bias;
    float4* ov = (float4*)(out + (size_t)node * F);
    #pragma unroll
    for (int v = 0; v < V; v++) {
        float4 b = bv[lane + 32 * v];
        float4 o = make_float4(acc[v].x + b.x, acc[v].y + b.y,
                               acc[v].z + b.z, acc[v].w + b.w);
        if (LAYER == 0) {
            o.x = fmaxf(o.x, 0.f); o.y = fmaxf(o.y, 0.f);
            o.z = fmaxf(o.z, 0.f); o.w = fmaxf(o.w, 0.f);
        }
        ov[lane + 32 * v] = o;
    }
}

// ---------------------------------------------------------------------------
// launch — inputs identified by element count (order-proof)
// ---------------------------------------------------------------------------
extern "C" void kernel_launch(void* const* d_in, const int* in_sizes, int n_in,
                              void* d_out, int out_size) {
    const float* x  = nullptr;
    const void*  ei = nullptr;
    const float* W1 = nullptr;
    const float* b1 = nullptr;
    const float* W2 = nullptr;
    const float* b2 = nullptr;

    for (int i = 0; i < n_in; i++) {
        switch (in_sizes[i]) {
            case NN * FIN:   x  = (const float*)d_in[i]; break;
            case 2 * NE:     ei = d_in[i];               break;
            case FIN * FH:   W1 = (const float*)d_in[i]; break;
            case FH:         b1 = (const float*)d_in[i]; break;
            case FH * FO:    W2 = (const float*)d_in[i]; break;
            case FO:         b2 = (const float*)d_in[i]; break;
            default: break;
        }
    }
    float* out = (float*)d_out;

    const int T = 256;

    k_detect   <<<1, 32>>>(ei);
    k_init     <<<(NN + T - 1) / T, T>>>();
    k_deg_count<<<(NE + T - 1) / T, T>>>(ei);
    k_dinv     <<<(NN + T - 1) / T, T>>>();
    k_scan     <<<1, 1024>>>();
    k_fill     <<<(NE + T - 1) / T, T>>>(ei);

    // layer 1: h1 = x @ W1 ; agg1 = relu(A_hat h1 + b1)
    {
        dim3 grid(FH / 128, (NN + 127) / 128);
        sgemm128<<<grid, 256>>>(x, W1, 0, NN, FH, FIN);
    }
    k_gather<0><<<((size_t)NN * 32 + T - 1) / T, T>>>(b1, nullptr);

    // layer 2: h2 = agg1 @ W2 ; out = A_hat h2 + b2
    {
        dim3 grid(FO / 128, (NN + 127) / 128);
        sgemm128<<<grid, 256>>>(nullptr, W2, 1, NN, FO, FH);
    }
    k_gather<1><<<((size_t)NN * 32 + T - 1) / T, T>>>(b2, out);
}

// round 7
// speedup vs baseline: 1.3474x; 1.0009x over previous
#include <cuda_runtime.h>
#include <stdint.h>

#define NN  50000
#define NE  800000
#define FIN 512
#define FH  256
#define FO  128

// ---- scratch: __device__ globals ----
__device__ int   g_is64;
__device__ __align__(16) float g_dinv[NN];
__device__ __align__(16) int   g_cnt [NN];
__device__ __align__(16) int   g_off [NN + 1];
__device__ __align__(16) int   g_fill[NN];
__device__ __align__(16) int   g_csr_src[NE];
__device__ __align__(16) float g_csr_w  [NE];
__device__ __align__(16) float g_h1  [(size_t)NN * FH];
__device__ __align__(16) float g_agg1[(size_t)NN * FH];
__device__ __align__(16) float g_h2  [(size_t)NN * FO];

// ---------------------------------------------------------------------------
// edge dtype detect (parallel, 2048 samples) + decode
// ---------------------------------------------------------------------------
__global__ void k_detect(const void* __restrict__ ei) {
    const long long* p = (const long long*)ei;
    int lane = threadIdx.x;
    int bad = 0;
    #pragma unroll 4
    for (int i = lane; i < 2048; i += 32) {
        long long v = p[i];
        if (v < 0 || v >= NN) bad = 1;
    }
    unsigned m = __ballot_sync(0xffffffffu, bad);
    if (lane == 0) g_is64 = (m == 0);
}

__device__ __forceinline__ unsigned eidx(const void* __restrict__ ei, size_t idx) {
    if (g_is64) return (unsigned)((const long long*)ei)[idx];
    return (unsigned)((const int*)ei)[idx];
}

// ---------------------------------------------------------------------------
// degree / normalization / CSR build
// ---------------------------------------------------------------------------
__global__ void k_init() {
    int i = blockIdx.x * blockDim.x + threadIdx.x;
    if (i < NN) { g_cnt[i] = 0; g_fill[i] = 0; }
}

__global__ void k_deg_count(const void* __restrict__ ei) {
    int i = blockIdx.x * blockDim.x + threadIdx.x;
    if (i < NE) {
        unsigned d = eidx(ei, (size_t)NE + i);
        if (d < NN) atomicAdd(&g_cnt[d], 1);
    }
}

__global__ void k_dinv() {
    int i = blockIdx.x * blockDim.x + threadIdx.x;
    if (i < NN) g_dinv[i] = rsqrtf((float)(g_cnt[i] + 1));   // +1 self-loop
}

// single-block exclusive scan of g_cnt -> g_off
__global__ void k_scan() {
    __shared__ int sh[1024];
    __shared__ int carry;
    const int tid = threadIdx.x;
    if (tid == 0) carry = 0;
    __syncthreads();

    for (int base = 0; base < NN; base += 1024) {
        int i = base + tid;
        int v = (i < NN) ? g_cnt[i] : 0;
        sh[tid] = v;
        __syncthreads();
        for (int ofs = 1; ofs < 1024; ofs <<= 1) {
            int t = (tid >= ofs) ? sh[tid - ofs] : 0;
            __syncthreads();
            sh[tid] += t;
            __syncthreads();
        }
        if (i < NN) g_off[i] = carry + sh[tid] - v;
        __syncthreads();
        if (tid == 1023) carry += sh[1023];
        __syncthreads();
    }
    if (tid == 0) g_off[NN] = carry;
}

__global__ void k_fill(const void* __restrict__ ei) {
    int i = blockIdx.x * blockDim.x + threadIdx.x;
    if (i < NE) {
        unsigned s = eidx(ei, i);
        unsigned d = eidx(ei, (size_t)NE + i);
        if (s < NN && d < NN) {
            int pos = g_off[d] + atomicAdd(&g_fill[d], 1);
            if (pos < NE) {
                g_csr_src[pos] = (int)s;
                g_csr_w[pos]   = g_dinv[s] * g_dinv[d];
            }
        }
    }
}

// ---------------------------------------------------------------------------
// fp32 SGEMM: C = A[M,K] @ B[K,N]; BM=BN=128, BK=16, 256 thr, 8x8 microtile
// layer 0: A = x (param), C = g_h1 ;  layer 1: A = g_agg1, C = g_h2
// ---------------------------------------------------------------------------
#define SPAD 132   // 128 + 4 padding (16B-aligned rows: 132*4=528=33*16)

__global__ void __launch_bounds__(256, 2)
sgemm128(const float* __restrict__ Aext, const float* __restrict__ B,
         int layer, int M, int N, int K) {
    const float* A = (layer == 0) ? Aext : (const float*)g_agg1;
    float*       C = (layer == 0) ? g_h1 : g_h2;

    __shared__ float As[16][SPAD];   // [k][m]
    __shared__ float Bs[16][SPAD];   // [k][n]

    const int tid = threadIdx.x;
    const int tx  = tid & 15;        // 0..15 -> n
    const int ty  = tid >> 4;        // 0..15 -> m
    const int row0 = blockIdx.y * 128;
    const int col0 = blockIdx.x * 128;

    float acc[8][8] = {};

    for (int k0 = 0; k0 < K; k0 += 16) {
        // load A tile 128x16 (2 float4 per thread), store transposed
        #pragma unroll
        for (int i = 0; i < 2; i++) {
            int idx = tid + i * 256;         // 0..511
            int r  = idx >> 2;               // 0..127
            int kq = idx & 3;                // 0..3 (float4 within k)
            int gr = row0 + r;
            float4 av = (gr < M) ? *(const float4*)&A[(size_t)gr * K + k0 + kq * 4]
                                 : make_float4(0.f, 0.f, 0.f, 0.f);
            As[kq * 4 + 0][r] = av.x;
            As[kq * 4 + 1][r] = av.y;
            As[kq * 4 + 2][r] = av.z;
            As[kq * 4 + 3][r] = av.w;
        }
        // load B tile 16x128 (2 float4 per thread), contiguous
        #pragma unroll
        for (int i = 0; i < 2; i++) {
            int idx = tid + i * 256;         // 0..511
            int rb = idx >> 5;               // 0..15
            int cb = idx & 31;               // 0..31
            float4 bv = *(const float4*)&B[(size_t)(k0 + rb) * N + col0 + cb * 4];
            *(float4*)&Bs[rb][cb * 4] = bv;
        }
        __syncthreads();

        #pragma unroll
        for (int kk = 0; kk < 16; kk++) {
            float4 a0 = *(const float4*)&As[kk][ty * 8];
            float4 a1 = *(const float4*)&As[kk][ty * 8 + 4];
            float4 b0 = *(const float4*)&Bs[kk][tx * 8];
            float4 b1 = *(const float4*)&Bs[kk][tx * 8 + 4];
            float a[8] = {a0.x, a0.y, a0.z, a0.w, a1.x, a1.y, a1.z, a1.w};
            float b[8] = {b0.x, b0.y, b0.z, b0.w, b1.x, b1.y, b1.z, b1.w};
            #pragma unroll
            for (int i = 0; i < 8; i++)
                #pragma unroll
                for (int j = 0; j < 8; j++)
                    acc[i][j] += a[i] * b[j];
        }
        __syncthreads();
    }

    // store 8x8 per thread (two float4 per row)
    #pragma unroll
    for (int i = 0; i < 8; i++) {
        int r = row0 + ty * 8 + i;
        if (r < M) {
            float4 o0 = make_float4(acc[i][0], acc[i][1], acc[i][2], acc[i][3]);
            float4 o1 = make_float4(acc[i][4], acc[i][5], acc[i][6], acc[i][7]);
            *(float4*)&C[(size_t)r * N + col0 + tx * 8]     = o0;
            *(float4*)&C[(size_t)r * N + col0 + tx * 8 + 4] = o1;
        }
    }
}

// ---------------------------------------------------------------------------
// CSR gather: out[i,:] = dinv[i]^2*h[i,:] + sum_e w_e*h[src_e,:] + bias
// ---------------------------------------------------------------------------
template<int LAYER>
__global__ void k_gather(const float* __restrict__ bias,
                         float* __restrict__ outext) {
    constexpr int F = (LAYER == 0) ? FH : FO;
    constexpr int V = F / 128;
    const float* h   = (LAYER == 0) ? (const float*)g_h1 : (const float*)g_h2;
    float*       out = (LAYER == 0) ? g_agg1 : outext;

    int node = (blockIdx.x * blockDim.x + threadIdx.x) >> 5;
    int lane = threadIdx.x & 31;
    if (node >= NN) return;

    float4 acc[V];
    float wi = g_dinv[node];
    wi *= wi;
    const float4* hr = (const float4*)(h + (size_t)node * F);
    #pragma unroll
    for (int v = 0; v < V; v++) {
        float4 t = hr[lane + 32 * v];
        acc[v] = make_float4(wi * t.x, wi * t.y, wi * t.z, wi * t.w);
    }

    int beg = g_off[node];
    int end = beg + g_cnt[node];
    for (int e = beg; e < end; e++) {
        int   s = g_csr_src[e];
        float w = g_csr_w[e];
        const float4* sr = (const float4*)(h + (size_t)s * F);
        #pragma unroll
        for (int v = 0; v < V; v++) {
            float4 t = sr[lane + 32 * v];
            acc[v].x += w * t.x; acc[v].y += w * t.y;
            acc[v].z += w * t.z; acc[v].w += w * t.w;
        }
    }

    const float4* bv = (const float4*)bias;
    float4* ov = (float4*)(out + (size_t)node * F);
    #pragma unroll
    for (int v = 0; v < V; v++) {
        float4 b = bv[lane + 32 * v];
        float4 o = make_float4(acc[v].x + b.x, acc[v].y + b.y,
                               acc[v].z + b.z, acc[v].w + b.w);
        if (LAYER == 0) {
            o.x = fmaxf(o.x, 0.f); o.y = fmaxf(o.y, 0.f);
            o.z = fmaxf(o.z, 0.f); o.w = fmaxf(o.w, 0.f);
        }
        ov[lane + 32 * v] = o;
    }
}

// ---------------------------------------------------------------------------
// launch — inputs identified by element count (order-proof)
// ---------------------------------------------------------------------------
extern "C" void kernel_launch(void* const* d_in, const int* in_sizes, int n_in,
                              void* d_out, int out_size) {
    const float* x  = nullptr;
    const void*  ei = nullptr;
    const float* W1 = nullptr;
    const float* b1 = nullptr;
    const float* W2 = nullptr;
    const float* b2 = nullptr;

    for (int i = 0; i < n_in; i++) {
        switch (in_sizes[i]) {
            case NN * FIN:   x  = (const float*)d_in[i]; break;
            case 2 * NE:     ei = d_in[i];               break;
            case FIN * FH:   W1 = (const float*)d_in[i]; break;
            case FH:         b1 = (const float*)d_in[i]; break;
            case FH * FO:    W2 = (const float*)d_in[i]; break;
            case FO:         b2 = (const float*)d_in[i]; break;
            default: break;
        }
    }
    float* out = (float*)d_out;

    const int T = 256;

    k_detect   <<<1, 32>>>(ei);
    k_init     <<<(NN + T - 1) / T, T>>>();
    k_deg_count<<<(NE + T - 1) / T, T>>>(ei);
    k_dinv     <<<(NN + T - 1) / T, T>>>();
    k_scan     <<<1, 1024>>>();
    k_fill     <<<(NE + T - 1) / T, T>>>(ei);

    // layer 1: h1 = x @ W1 ; agg1 = relu(A_hat h1 + b1)
    {
        dim3 grid(FH / 128, (NN + 127) / 128);
        sgemm128<<<grid, 256>>>(x, W1, 0, NN, FH, FIN);
    }
    k_gather<0><<<((size_t)NN * 32 + T - 1) / T, T>>>(b1, nullptr);

    // layer 2: h2 = agg1 @ W2 ; out = A_hat h2 + b2
    {
        dim3 grid(FO / 128, (NN + 127) / 128);
        sgemm128<<<grid, 256>>>(nullptr, W2, 1, NN, FO, FH);
    }
    k_gather<1><<<((size_t)NN * 32 + T - 1) / T, T>>>(b2, out);
}